// round 11
// baseline (speedup 1.0000x reference)
#include <cuda_runtime.h>

// out[j]     = dot(X[r1(j)], p), r1(j) = inds1[2j]*28 + inds1[2j+1], j in [0,100)
// out[100+j] = dot(Y[r2(j)], p)
// R8's proven shape (1024-thread blocks, 8 front-batched LDG.128/thread) at
// half-dot grain: 200 dots x 2 segments = 400 CTAs -> per-SM CTA count {2,3}
// instead of {1,2} waves => parallel phase 1.5*T_half vs 2*T_full.
// Spread per-dot counter: 2nd arriver sums the 2 partials (fixed order).

#define Q      32768
#define QV     (Q / 4)       // 8192 float4 per row
#define NSEG   2
#define SEGF4  (QV / NSEG)   // 4096 float4 per segment
#define NT     1024
#define W_DIM  28
#define NDOTS  200
#define NBLK   (NDOTS * NSEG)  // 400

__device__ float        g_partial[NBLK];
__device__ unsigned int g_cnt[NDOTS];   // zero-init; finisher resets each launch

__device__ __forceinline__ float dot4(float4 a, float4 b) {
    return a.x * b.x + a.y * b.y + a.z * b.z + a.w * b.w;
}

__global__ __launch_bounds__(NT, 1)
void half_dot_kernel(const float* __restrict__ X,
                     const float* __restrict__ Y,
                     const float* __restrict__ p,
                     const int*   __restrict__ inds1,
                     const int*   __restrict__ inds2,
                     float* __restrict__ out)
{
    const int b   = blockIdx.x;        // 0..399
    const int j   = b >> 1;            // dot 0..199
    const int seg = b & 1;

    const bool second = (j >= 100);
    const int jj = second ? (j - 100) : j;
    const int* __restrict__ inds = second ? inds2 : inds1;
    const float* __restrict__ M  = second ? Y : X;

    const float4* __restrict__ pv = reinterpret_cast<const float4*>(p);
    const int i0 = seg * SEGF4 + threadIdx.x;

    // p loads first (independent of inds chain).
    float4 p0 = pv[i0];
    float4 p1 = pv[i0 +     NT];
    float4 p2 = pv[i0 + 2 * NT];
    float4 p3 = pv[i0 + 3 * NT];

    const int r = inds[2 * jj] * W_DIM + inds[2 * jj + 1];
    const float4* __restrict__ row = reinterpret_cast<const float4*>(M + (size_t)r * Q);

    float4 a0 = row[i0];
    float4 a1 = row[i0 +     NT];
    float4 a2 = row[i0 + 2 * NT];
    float4 a3 = row[i0 + 3 * NT];

    float sum = dot4(a0, p0);
    sum += dot4(a1, p1);
    sum += dot4(a2, p2);
    sum += dot4(a3, p3);

    // warp reduce
    #pragma unroll
    for (int off = 16; off > 0; off >>= 1)
        sum += __shfl_xor_sync(0xFFFFFFFFu, sum, off);

    __shared__ float warp_sums[NT / 32];
    const int lane = threadIdx.x & 31;
    const int wid  = threadIdx.x >> 5;
    if (lane == 0) warp_sums[wid] = sum;
    __syncthreads();

    if (wid == 0) {
        float s = (lane < NT / 32) ? warp_sums[lane] : 0.0f;
        #pragma unroll
        for (int off = 16; off > 0; off >>= 1)
            s += __shfl_xor_sync(0xFFFFFFFFu, s, off);

        if (lane == 0) {
            g_partial[j * NSEG + seg] = s;
            __threadfence();                            // publish partial
            unsigned int t = atomicAdd(&g_cnt[j], 1u);  // 200 spread counters
            if (t == NSEG - 1) {
                __threadfence();                        // acquire peer partial
                const volatile float* gp = g_partial + j * NSEG;
                out[j] = gp[0] + gp[1];                 // fixed order
                g_cnt[j] = 0;                           // reset for replay
            }
        }
    }
}

extern "C" void kernel_launch(void* const* d_in, const int* in_sizes, int n_in,
                              void* d_out, int out_size)
{
    const float* X   = (const float*)d_in[0];
    const float* Y   = (const float*)d_in[1];
    const float* p   = (const float*)d_in[2];
    const int* inds1 = (const int*)d_in[3];
    const int* inds2 = (const int*)d_in[4];
    float* out       = (float*)d_out;

    half_dot_kernel<<<NBLK, NT>>>(X, Y, p, inds1, inds2, out);
}

// round 12
// speedup vs baseline: 1.5351x; 1.5351x over previous
#include <cuda_runtime.h>

// out[j]     = dot(X[r1(j)], p), r1(j) = inds1[2j]*28 + inds1[2j+1], j in [0,100)
// out[100+j] = dot(Y[r2(j)], p)
// 200 blocks x 512 threads, __launch_bounds__(512,2) caps regs at 64 so TWO
// CTAs fit per SM (512*64*2 = 65536 = full RF): all 200 dots run in a single
// wave (vs R8's 148+52 two-wave schedule) with the same 8-warps/SMSP residency.
// Per thread: 16 float4 of row + p in 4 sequential batches of 8 independent
// LDG.128 (32 data regs in flight). Direct write, no atomics/partials.

#define Q      32768
#define QV     (Q / 4)      // 8192 float4 per row
#define NT     512
#define W_DIM  28
#define NDOTS  200

__device__ __forceinline__ float dot4(float4 a, float4 b) {
    return a.x * b.x + a.y * b.y + a.z * b.z + a.w * b.w;
}

__global__ __launch_bounds__(NT, 2)
void dot_onewave_kernel(const float* __restrict__ X,
                        const float* __restrict__ Y,
                        const float* __restrict__ p,
                        const int*   __restrict__ inds1,
                        const int*   __restrict__ inds2,
                        float* __restrict__ out)
{
    const int j = blockIdx.x;            // 0..199
    const bool second = (j >= 100);
    const int jj = second ? (j - 100) : j;
    const int* __restrict__ inds = second ? inds2 : inds1;
    const float* __restrict__ M  = second ? Y : X;

    const int r = inds[2 * jj] * W_DIM + inds[2 * jj + 1];

    const float4* __restrict__ row = reinterpret_cast<const float4*>(M + (size_t)r * Q);
    const float4* __restrict__ pv  = reinterpret_cast<const float4*>(p);

    const int t = threadIdx.x;           // 16 float4 per array per thread
    float sum = 0.0f;

    // 4 batches of (4 p + 4 row) independent LDG.128; 32 data regs in flight.
    #pragma unroll
    for (int b = 0; b < 4; b++) {
        const int i = t + b * 4 * NT;
        float4 p0 = pv[i];
        float4 p1 = pv[i +     NT];
        float4 p2 = pv[i + 2 * NT];
        float4 p3 = pv[i + 3 * NT];
        float4 a0 = row[i];
        float4 a1 = row[i +     NT];
        float4 a2 = row[i + 2 * NT];
        float4 a3 = row[i + 3 * NT];
        sum += dot4(a0, p0);
        sum += dot4(a1, p1);
        sum += dot4(a2, p2);
        sum += dot4(a3, p3);
    }

    // warp reduce
    #pragma unroll
    for (int off = 16; off > 0; off >>= 1)
        sum += __shfl_xor_sync(0xFFFFFFFFu, sum, off);

    __shared__ float warp_sums[NT / 32];
    const int lane = t & 31;
    const int wid  = t >> 5;
    if (lane == 0) warp_sums[wid] = sum;
    __syncthreads();

    if (wid == 0) {
        float s = (lane < NT / 32) ? warp_sums[lane] : 0.0f;
        #pragma unroll
        for (int off = 8; off > 0; off >>= 1)
            s += __shfl_xor_sync(0xFFFFFFFFu, s, off);
        if (lane == 0) out[j] = s;
    }
}

extern "C" void kernel_launch(void* const* d_in, const int* in_sizes, int n_in,
                              void* d_out, int out_size)
{
    const float* X   = (const float*)d_in[0];
    const float* Y   = (const float*)d_in[1];
    const float* p   = (const float*)d_in[2];
    const int* inds1 = (const int*)d_in[3];
    const int* inds2 = (const int*)d_in[4];
    float* out       = (float*)d_out;

    dot_onewave_kernel<<<NDOTS, NT>>>(X, Y, p, inds1, inds2, out);
}